// round 9
// baseline (speedup 1.0000x reference)
#include <cuda_runtime.h>

typedef unsigned long long ull;

#define SS   (320*512)      // text state buffer (rows*H)

// -------- device scratch (no allocation allowed) --------
__device__ float g_Xv1[1280L*2048];     // [B*F, 4H] rows (b*20+f): vf@Wih_v1^T + b_v1
__device__ float g_Xt1[6400L*2048];     // [L*BN, 4H] rows (l*320+sortedRow)
__device__ float g_part[8L*64*2048];    // split-K partials (video cells)
__device__ float g_vh1[64*512];         // video states (in-place)
__device__ float g_vc1[64*512];
__device__ float g_vh2[64*512];
__device__ float g_vc2[64*512];
__device__ float g_h1[2*SS];            // text ping-pong (sorted rows)
__device__ float g_c1[2*SS];
__device__ float g_h2[2*SS];
__device__ float g_c2[2*SS];
__device__ float g_nh1[SS];
__device__ float g_nc1[SS];
__device__ float g_fe[320*1024];
__device__ int   g_perm[320];           // sorted row -> original row
__device__ int   g_qs[320];             // qlen per sorted row (desc)

// ---- packed f32x2 helpers (lowered to 2xFFMA on sm_100a) ----
__device__ __forceinline__ ull pk2(float lo, float hi) {
    ull r;
    asm("mov.b64 %0, {%1, %2};" : "=l"(r) : "f"(lo), "f"(hi));
    return r;
}
__device__ __forceinline__ void upk2(ull v, float& lo, float& hi) {
    asm("mov.b64 {%0, %1}, %2;" : "=f"(lo), "=f"(hi) : "l"(v));
}
#define FMA2(acc, a, b) asm("fma.rn.f32x2 %0, %1, %2, %3;" : "=l"(acc) : "l"(a), "l"(b), "l"(acc))

__device__ __forceinline__ float sigf(float x) { return 1.f / (1.f + expf(-x)); }

// =====================================================================
// sortq: sort 64 batches by qlen descending; build row perm + qs.
// =====================================================================
__global__ void sortq(const int* __restrict__ qlen,
                      int* __restrict__ perm, int* __restrict__ qs)
{
    if (threadIdx.x == 0) {
        int idx[64];
        for (int i = 0; i < 64; i++) idx[i] = i;
        for (int i = 1; i < 64; i++) {
            int v = idx[i], qv = qlen[v], j = i - 1;
            while (j >= 0 && qlen[idx[j]] < qv) { idx[j + 1] = idx[j]; j--; }
            idx[j + 1] = v;
        }
        for (int s = 0; s < 320; s++) {
            int b = idx[s / 5];
            perm[s] = b * 5 + (s % 5);
            qs[s] = qlen[b];
        }
    }
}

// =====================================================================
// vgemm: split-K video cell GEMM (unchanged from R6, proven)
// =====================================================================
template<int KS, int CC>
__global__ __launch_bounds__(256)
void vgemm(const float* __restrict__ A, const float* __restrict__ A2,
           const float* __restrict__ W, const float* __restrict__ W2,
           float* __restrict__ part)
{
    extern __shared__ float sm[];
    float* As = sm;
    float* Bs = sm + 64 * KS;

    const int tid = threadIdx.x;
    const int n0 = blockIdx.x * 128;
    const int kbase = blockIdx.y * KS;

#pragma unroll
    for (int z = 0; z < KS / 16; z++) {
        int c = tid + z * 256;
        int m = c / (KS / 4), k4 = c % (KS / 4);
        int gk = kbase + k4 * 4;
        float4 v;
        if (!CC || gk < 512) v = *(const float4*)&A[m * 512 + gk];
        else                 v = *(const float4*)&A2[m * 512 + gk - 512];
        *(float4*)&As[m * KS + k4 * 4] = v;
    }
#pragma unroll
    for (int z = 0; z < KS / 8; z++) {
        int c = tid + z * 256;
        int n = c / (KS / 4), k4 = c % (KS / 4);
        int gk = kbase + k4 * 4;
        float4 v;
        if (!CC || gk < 512) v = *(const float4*)&W[(long)(n0 + n) * 512 + gk];
        else                 v = *(const float4*)&W2[(long)(n0 + n) * 512 + gk - 512];
        int nsw = n ^ ((k4 & 15) * 2);
        Bs[(k4 * 4 + 0) * 128 + nsw] = v.x;
        Bs[(k4 * 4 + 1) * 128 + nsw] = v.y;
        Bs[(k4 * 4 + 2) * 128 + nsw] = v.z;
        Bs[(k4 * 4 + 3) * 128 + nsw] = v.w;
    }
    __syncthreads();

    const int tx = tid & 15, ty = tid >> 4;
    ull acc[4][4];
#pragma unroll
    for (int rm = 0; rm < 4; rm++)
#pragma unroll
        for (int s = 0; s < 4; s++) acc[rm][s] = 0ull;

#pragma unroll 4
    for (int kk = 0; kk < KS; kk++) {
        const int swr = ((kk >> 2) & 15) * 2;
        ull b[4];
#pragma unroll
        for (int s = 0; s < 4; s++)
            b[s] = *(const ull*)&Bs[kk * 128 + ((tx * 2 + s * 32) ^ swr)];
#pragma unroll
        for (int rm = 0; rm < 4; rm++) {
            float a = As[(ty * 4 + rm) * KS + kk];
            ull ad = pk2(a, a);
            FMA2(acc[rm][0], ad, b[0]);
            FMA2(acc[rm][1], ad, b[1]);
            FMA2(acc[rm][2], ad, b[2]);
            FMA2(acc[rm][3], ad, b[3]);
        }
    }

    float* op = part + (long)blockIdx.y * (64 * 2048) + n0;
#pragma unroll
    for (int rm = 0; rm < 4; rm++) {
        int m = ty * 4 + rm;
#pragma unroll
        for (int s = 0; s < 4; s++) {
            float lo, hi;
            upk2(acc[rm][s], lo, hi);
            *(float2*)&op[(long)m * 2048 + tx * 2 + s * 32] = make_float2(lo, hi);
        }
    }
}

// video pointwise: sum 8 partials (+xpre or +bias), LSTM update in-place.
__global__ void vpw(const float* __restrict__ part,
                    const float* __restrict__ xpre, long xstride,
                    const float* __restrict__ bias,
                    float* __restrict__ h, float* __restrict__ c)
{
    int idx = blockIdx.x * 256 + threadIdx.x;
    int m = idx >> 9, j = idx & 511;
    float g[4];
#pragma unroll
    for (int gi = 0; gi < 4; gi++) {
        int col = gi * 512 + j;
        float s = bias ? bias[col] : xpre[(long)m * xstride + col];
#pragma unroll
        for (int z = 0; z < 8; z++)
            s += part[(long)z * 64 * 2048 + (long)m * 2048 + col];
        g[gi] = s;
    }
    float cc = sigf(g[1]) * c[idx] + sigf(g[0]) * tanhf(g[2]);
    c[idx] = cc;
    h[idx] = sigf(g[3]) * tanhf(cc);
}

// =====================================================================
// cell_k3: fused text LSTM cell (R6 core) + qlen-sorted early exit.
// qlen = per-sorted-row qlen (g_qs); skip block when t > qs[m0]
// (rows sorted desc -> row m0 holds the block max).
// =====================================================================
template<int TY, int TX, int RM, int RJ, int CC, int HX, int HB, int MK>
__global__ __launch_bounds__(256)
void cell_k3(const float* __restrict__ A, const float* __restrict__ A2,
             const float* __restrict__ W, const float* __restrict__ W2,
             const float* __restrict__ bias,
             const float* __restrict__ xpre, int xstride,
             const float* __restrict__ c_in,
             float* __restrict__ h_out, float* __restrict__ c_out,
             const float* __restrict__ nc1p,
             const float* __restrict__ h1_in, const float* __restrict__ c1_in,
             float* __restrict__ h1_o, float* __restrict__ c1_o,
             const int* __restrict__ qlen, int t)
{
    constexpr int TM = TY * RM;
    constexpr int TJ = TX * RJ;
    constexpr int GC = 4 * TJ;
    constexpr int K  = CC ? 1024 : 512;
    constexpr int BK = 16;
    constexpr int ASTR = TM + 4;
    constexpr int BSTR = GC + 4;
    constexpr int NCA = (TM * 4) / 256;
    constexpr int NCB = (GC * 4 + 255) / 256;

    // ragged early exit (safe: at t == qlen the freeze-commit ran, so both
    // ping buffers already hold the frozen state before any skip happens)
    if (t > __ldg(&qlen[blockIdx.y * TM])) return;

    __shared__ float As[2][BK * ASTR];
    __shared__ float Bs[2][BK * BSTR];

    const int tid = threadIdx.x;
    const int tx  = tid % TX;
    const int ty  = tid / TX;
    const int m0  = blockIdx.y * TM;
    const int j0  = blockIdx.x * TJ;

    float4 pa[NCA], pb[NCB];

    auto ldg = [&](int kb) {
#pragma unroll
        for (int z = 0; z < NCA; z++) {
            int i = tid + z * 256;
            int row = i >> 2, kq = (i & 3) * 4;
            int m = m0 + row, k = kb + kq;
            pa[z] = CC ? ((k < 512) ? *(const float4*)&A[(long)m * 512 + k]
                                    : *(const float4*)&A2[(long)m * 512 + (k - 512)])
                       : *(const float4*)&A[(long)m * 512 + k];
        }
#pragma unroll
        for (int z = 0; z < NCB; z++) {
            int i = tid + z * 256;
            if (i < GC * 4) {
                int r = i >> 2, kq = (i & 3) * 4;
                int jl = r >> 2, g = r & 3;
                int wr = g * 512 + j0 + jl, k = kb + kq;
                pb[z] = CC ? ((k < 512) ? *(const float4*)&W[(long)wr * 512 + k]
                                        : *(const float4*)&W2[(long)wr * 512 + (k - 512)])
                           : *(const float4*)&W[(long)wr * 512 + k];
            }
        }
    };
    auto sts = [&](int s) {
#pragma unroll
        for (int z = 0; z < NCA; z++) {
            int i = tid + z * 256;
            int row = i >> 2, kq = (i & 3) * 4;
            As[s][(kq + 0) * ASTR + row] = pa[z].x;
            As[s][(kq + 1) * ASTR + row] = pa[z].y;
            As[s][(kq + 2) * ASTR + row] = pa[z].z;
            As[s][(kq + 3) * ASTR + row] = pa[z].w;
        }
#pragma unroll
        for (int z = 0; z < NCB; z++) {
            int i = tid + z * 256;
            if (i < GC * 4) {
                int r = i >> 2, kq = (i & 3) * 4;
                Bs[s][(kq + 0) * BSTR + r] = pb[z].x;
                Bs[s][(kq + 1) * BSTR + r] = pb[z].y;
                Bs[s][(kq + 2) * BSTR + r] = pb[z].z;
                Bs[s][(kq + 3) * BSTR + r] = pb[z].w;
            }
        }
    };

    ull acc[RM][RJ][2];
#pragma unroll
    for (int im = 0; im < RM; im++)
#pragma unroll
        for (int ij = 0; ij < RJ; ij++) { acc[im][ij][0] = 0ull; acc[im][ij][1] = 0ull; }

    ldg(0); sts(0); __syncthreads();
    constexpr int NKT = K / BK;
    for (int kt = 0; kt < NKT; kt++) {
        const int s = kt & 1;
        if (kt + 1 < NKT) ldg((kt + 1) * BK);
#pragma unroll
        for (int kk = 0; kk < BK; kk++) {
            ull ad[RM];
            if (RM == 4) {
                const float4 av = *(const float4*)&As[s][kk * ASTR + ty * RM];
                ad[0] = pk2(av.x, av.x); ad[1] = pk2(av.y, av.y);
                ad[2] = pk2(av.z, av.z); ad[3] = pk2(av.w, av.w);
            } else {
                const float2 av = *(const float2*)&As[s][kk * ASTR + ty * RM];
                ad[0] = pk2(av.x, av.x); ad[1] = pk2(av.y, av.y);
            }
#pragma unroll
            for (int ij = 0; ij < RJ; ij++) {
                const ulonglong2 bv =
                    *(const ulonglong2*)&Bs[s][kk * BSTR + (tx * RJ + ij) * 4];
#pragma unroll
                for (int im = 0; im < RM; im++) {
                    FMA2(acc[im][ij][0], ad[im], bv.x);
                    FMA2(acc[im][ij][1], ad[im], bv.y);
                }
            }
        }
        if (kt + 1 < NKT) sts(s ^ 1);
        __syncthreads();
    }

#pragma unroll
    for (int im = 0; im < RM; im++) {
#pragma unroll
        for (int ij = 0; ij < RJ; ij++) {
            int m = m0 + ty * RM + im;
            int j = j0 + tx * RJ + ij;
            int idx = m * 512 + j;
            float vi, vf, vg, vo;
            upk2(acc[im][ij][0], vi, vf);
            upk2(acc[im][ij][1], vg, vo);
            if (HX) {
                const float* xr = xpre + (long)m * xstride;
                vi += xr[j]; vf += xr[512 + j]; vg += xr[1024 + j]; vo += xr[1536 + j];
            }
            if (HB) {
                vi += bias[j]; vf += bias[512 + j]; vg += bias[1024 + j]; vo += bias[1536 + j];
            }
            float c = sigf(vf) * c_in[idx] + sigf(vi) * tanhf(vg);
            float h = sigf(vo) * tanhf(c);
            if (!MK) {
                c_out[idx] = c;
                h_out[idx] = h;
            } else {
                bool upd = t < qlen[m];               // per-sorted-row qlen
                h_out[idx] = upd ? h : A2[idx];       // A2 = old h2
                c_out[idx] = upd ? c : c_in[idx];     // c_in = old c2
                h1_o[idx]  = upd ? A[idx] : h1_in[idx];
                c1_o[idx]  = upd ? nc1p[idx] : c1_in[idx];
            }
        }
    }
}

// =====================================================================
// sgemm3 (R6, proven): 128x64xK GEMM, BK=16 double-buffered, f32x2.
// AM: 0 = direct, 2 = embedding gather (SORTED row space via perm).
// =====================================================================
template<int AM>
__global__ __launch_bounds__(256)
void sgemm3(const float* __restrict__ A, const float* __restrict__ W,
            const float* __restrict__ bias, float* __restrict__ out,
            int Kfull, int lda,
            const int* __restrict__ ques, const float* __restrict__ emb,
            const int* __restrict__ perm)
{
    constexpr int BK = 16, ASTR = 132, BSTR = 68;
    __shared__ float As[2][BK * ASTR];
    __shared__ float Bs[2][BK * BSTR];

    const int tid = threadIdx.x;
    const int tx  = tid & 15;
    const int ty  = tid >> 4;
    const int m0  = blockIdx.y * 128;
    const int n0  = blockIdx.x * 64;

    float4 pa[2], pb;

    auto ldg = [&](int kb) {
#pragma unroll
        for (int z = 0; z < 2; z++) {
            int c = tid + z * 256, row = c >> 2, kq = (c & 3) * 4;
            int m = m0 + row, k = kb + kq;
            if (AM == 0) {
                pa[z] = *(const float4*)&A[(long)m * lda + k];
            } else {
                int qq = m % 320, l = m / 320;
                long tb = (long)ques[perm[qq] * 20 + l] * 300;
                float v[4];
#pragma unroll
                for (int i = 0; i < 4; i++) {
                    int kk = k + i;
                    v[i] = (kk < Kfull) ? emb[tb + kk] : 0.f;
                }
                pa[z] = make_float4(v[0], v[1], v[2], v[3]);
            }
        }
        {
            int c = tid, r = c >> 2, kq = (c & 3) * 4;
            int n = n0 + r, k = kb + kq;
            if (AM == 0) {
                pb = *(const float4*)&W[(long)n * lda + k];
            } else {
                float v[4];
#pragma unroll
                for (int i = 0; i < 4; i++)
                    v[i] = (k + i < Kfull) ? W[(long)n * Kfull + k + i] : 0.f;
                pb = make_float4(v[0], v[1], v[2], v[3]);
            }
        }
    };
    auto sts = [&](int s) {
#pragma unroll
        for (int z = 0; z < 2; z++) {
            int c = tid + z * 256, row = c >> 2, kq = (c & 3) * 4;
            As[s][(kq + 0) * ASTR + row] = pa[z].x;
            As[s][(kq + 1) * ASTR + row] = pa[z].y;
            As[s][(kq + 2) * ASTR + row] = pa[z].z;
            As[s][(kq + 3) * ASTR + row] = pa[z].w;
        }
        {
            int c = tid, r = c >> 2, kq = (c & 3) * 4;
            Bs[s][(kq + 0) * BSTR + r] = pb.x;
            Bs[s][(kq + 1) * BSTR + r] = pb.y;
            Bs[s][(kq + 2) * BSTR + r] = pb.z;
            Bs[s][(kq + 3) * BSTR + r] = pb.w;
        }
    };

    ull acc[8][2];
#pragma unroll
    for (int i = 0; i < 8; i++) { acc[i][0] = 0ull; acc[i][1] = 0ull; }

    ldg(0); sts(0); __syncthreads();
    const int nkt = (Kfull + BK - 1) / BK;
    for (int kt = 0; kt < nkt; kt++) {
        const int s = kt & 1;
        if (kt + 1 < nkt) ldg((kt + 1) * BK);
#pragma unroll
        for (int kk = 0; kk < BK; kk++) {
            const float4 a0 = *(const float4*)&As[s][kk * ASTR + ty * 8];
            const float4 a1 = *(const float4*)&As[s][kk * ASTR + ty * 8 + 4];
            const ulonglong2 bv = *(const ulonglong2*)&Bs[s][kk * BSTR + tx * 4];
            float av[8] = { a0.x, a0.y, a0.z, a0.w, a1.x, a1.y, a1.z, a1.w };
#pragma unroll
            for (int im = 0; im < 8; im++) {
                ull ad = pk2(av[im], av[im]);
                FMA2(acc[im][0], ad, bv.x);
                FMA2(acc[im][1], ad, bv.y);
            }
        }
        if (kt + 1 < nkt) sts(s ^ 1);
        __syncthreads();
    }

#pragma unroll
    for (int im = 0; im < 8; im++) {
        int m = m0 + ty * 8 + im;
        long ro = (long)m * 2048 + n0 + tx * 4;
        float v0, v1, v2, v3;
        upk2(acc[im][0], v0, v1);
        upk2(acc[im][1], v2, v3);
        if (bias) {
            v0 += bias[n0 + tx * 4 + 0]; v1 += bias[n0 + tx * 4 + 1];
            v2 += bias[n0 + tx * 4 + 2]; v3 += bias[n0 + tx * 4 + 3];
        }
        out[ro + 0] = v0; out[ro + 1] = v1; out[ro + 2] = v2; out[ro + 3] = v3;
    }
}

// broadcast video-final states [64,512] -> text-init [320,512] (sorted rows)
__global__ void bc_init(const float* __restrict__ sh1, const float* __restrict__ sc1,
                        const float* __restrict__ sh2, const float* __restrict__ sc2,
                        float* __restrict__ dh1, float* __restrict__ dc1,
                        float* __restrict__ dh2, float* __restrict__ dc2,
                        const int* __restrict__ perm)
{
    int idx = blockIdx.x * blockDim.x + threadIdx.x;
    if (idx >= 320 * 512) return;
    int q = idx >> 9, j = idx & 511;
    int s = (perm[q] / 5) * 512 + j;
    dh1[idx] = sh1[s]; dc1[idx] = sc1[s];
    dh2[idx] = sh2[s]; dc2[idx] = sc2[s];
}

// ---- decoder (sorted-space input, scatter to original rows) ----
__global__ __launch_bounds__(256)
void dec1_k(const float* __restrict__ A, const float* __restrict__ A2,
            const float* __restrict__ W, const float* __restrict__ bias,
            float* __restrict__ out, const int* __restrict__ perm)
{
    __shared__ float As[8][128];
    __shared__ float Bs[8][128];
    const int tid = threadIdx.x;
    const int r   = tid >> 1;
    const int kq  = (tid & 1) * 4;
    const int m0  = blockIdx.y * 128;
    const int n0  = blockIdx.x * 128;
    const int tx  = tid & 15;
    const int ty  = tid >> 4;
    const int m   = m0 + r;
    const int n   = n0 + r;

    float acc[8][8];
#pragma unroll
    for (int i = 0; i < 8; i++)
#pragma unroll
        for (int jj = 0; jj < 8; jj++) acc[i][jj] = 0.f;

    for (int kt = 0; kt < 128; kt++) {
        const int kb = kt * 8;
#pragma unroll
        for (int i = 0; i < 4; i++) {
            int k = kb + kq + i;
            As[kq + i][r] = (m < 320) ? ((k < 512) ? A[(long)m * 512 + k]
                                                   : A2[(long)m * 512 + (k - 512)]) : 0.f;
            Bs[kq + i][r] = W[(long)n * 1024 + k];
        }
        __syncthreads();
#pragma unroll
        for (int kk = 0; kk < 8; kk++) {
            float a[8], b[8];
#pragma unroll
            for (int i = 0; i < 8; i++) a[i] = As[kk][ty * 8 + i];
#pragma unroll
            for (int jj = 0; jj < 8; jj++) b[jj] = Bs[kk][tx * 8 + jj];
#pragma unroll
            for (int i = 0; i < 8; i++)
#pragma unroll
                for (int jj = 0; jj < 8; jj++) acc[i][jj] += a[i] * b[jj];
        }
        __syncthreads();
    }
#pragma unroll
    for (int i = 0; i < 8; i++) {
        int mm = m0 + ty * 8 + i;
        if (mm < 320) {
            long ro = (long)perm[mm] * 1024 + n0 + tx * 8;
#pragma unroll
            for (int jj = 0; jj < 8; jj++)
                out[ro + jj] = acc[i][jj] + bias[n0 + tx * 8 + jj];
        }
    }
}

__global__ void dec2_k(const float* __restrict__ fe, const float* __restrict__ w,
                       const float* __restrict__ b, float* __restrict__ out)
{
    int warp = (blockIdx.x * blockDim.x + threadIdx.x) >> 5;
    int lane = threadIdx.x & 31;
    if (warp >= 320) return;
    float s = 0.f;
    for (int k = lane; k < 1024; k += 32) s += fe[(long)warp * 1024 + k] * w[k];
#pragma unroll
    for (int o = 16; o; o >>= 1) s += __shfl_xor_sync(0xFFFFFFFFu, s, o);
    if (lane == 0) out[warp] = s + b[0];
}

__global__ void argmax_k(const float* __restrict__ outv, float* __restrict__ pred)
{
    int b = threadIdx.x;
    if (b < 64) {
        float best = outv[b * 5]; int bi = 0;
#pragma unroll
        for (int n = 1; n < 5; n++) {
            float v = outv[b * 5 + n];
            if (v > best) { best = v; bi = n; }
        }
        pred[b] = (float)bi;
    }
}

// ---------------- host orchestration ----------------
extern "C" void kernel_launch(void* const* d_in, const int* in_sizes, int n_in,
                              void* d_out, int out_size)
{
    const float* vf      = (const float*)d_in[0];
    const int*   ques    = (const int*)  d_in[1];
    const int*   qlen    = (const int*)  d_in[2];
    const float* embed   = (const float*)d_in[3];
    const float* Wih_t1  = (const float*)d_in[4];
    const float* Whh_t1  = (const float*)d_in[5];
    const float* b_t1    = (const float*)d_in[6];
    const float* Wih_t2  = (const float*)d_in[7];
    const float* Whh_t2  = (const float*)d_in[8];
    const float* b_t2    = (const float*)d_in[9];
    const float* Wih_v1  = (const float*)d_in[10];
    const float* Whh_v1  = (const float*)d_in[11];
    const float* b_v1    = (const float*)d_in[12];
    const float* Wih_v2  = (const float*)d_in[13];
    const float* Whh_v2  = (const float*)d_in[14];
    const float* b_v2    = (const float*)d_in[15];
    const float* dec1_w  = (const float*)d_in[16];
    const float* dec1_b  = (const float*)d_in[17];
    const float* dec2_w  = (const float*)d_in[18];
    const float* dec2_b  = (const float*)d_in[19];
    float* out = (float*)d_out;

    float *Xv1, *Xt1, *part, *vh1, *vc1, *vh2, *vc2;
    float *h1, *c1, *h2, *c2, *nh1, *nc1, *fe;
    int *perm, *qs;
    cudaGetSymbolAddress((void**)&Xv1, g_Xv1);
    cudaGetSymbolAddress((void**)&Xt1, g_Xt1);
    cudaGetSymbolAddress((void**)&part, g_part);
    cudaGetSymbolAddress((void**)&vh1, g_vh1);
    cudaGetSymbolAddress((void**)&vc1, g_vc1);
    cudaGetSymbolAddress((void**)&vh2, g_vh2);
    cudaGetSymbolAddress((void**)&vc2, g_vc2);
    cudaGetSymbolAddress((void**)&h1,  g_h1);
    cudaGetSymbolAddress((void**)&c1,  g_c1);
    cudaGetSymbolAddress((void**)&h2,  g_h2);
    cudaGetSymbolAddress((void**)&c2,  g_c2);
    cudaGetSymbolAddress((void**)&nh1, g_nh1);
    cudaGetSymbolAddress((void**)&nc1, g_nc1);
    cudaGetSymbolAddress((void**)&fe,  g_fe);
    cudaGetSymbolAddress((void**)&perm, g_perm);
    cudaGetSymbolAddress((void**)&qs,   g_qs);

    // zero video initial states
    cudaMemsetAsync(vh1, 0, 64 * 512 * sizeof(float));
    cudaMemsetAsync(vc1, 0, 64 * 512 * sizeof(float));
    cudaMemsetAsync(vh2, 0, 64 * 512 * sizeof(float));
    cudaMemsetAsync(vc2, 0, 64 * 512 * sizeof(float));

    // sort batches by qlen (desc) -> row perm + per-row qlen
    sortq<<<1, 32>>>(qlen, perm, qs);

    // Xv1 = vf @ Wih_v1^T + b_v1 : [1280, 2048], K=8192
    sgemm3<0><<<dim3(32, 10), 256>>>(vf, Wih_v1, b_v1, Xv1, 8192, 8192,
                                     nullptr, nullptr, nullptr);
    // Xt1 = emb @ Wih_t1^T + b_t1 in SORTED row space
    sgemm3<2><<<dim3(32, 50), 256>>>(nullptr, Wih_t1, b_t1, Xt1, 300, 300,
                                     ques, embed, perm);

    // smem attrs for video split-K cells
    const int smem1 = (64 * 64 + 64 * 128) * 4;
    const int smem2 = (64 * 128 + 128 * 128) * 4;
    cudaFuncSetAttribute(vgemm<64, 0>, cudaFuncAttributeMaxDynamicSharedMemorySize, smem1);
    cudaFuncSetAttribute(vgemm<128, 1>, cudaFuncAttributeMaxDynamicSharedMemorySize, smem2);

    // ---- video recurrence: split-K GEMM + pointwise, in-place states ----
    for (int t = 0; t < 20; t++) {
        vgemm<64, 0><<<dim3(16, 8), 256, smem1>>>(vh1, nullptr, Whh_v1, nullptr, part);
        vpw<<<128, 256>>>(part, Xv1 + (long)t * 2048, 20 * 2048, nullptr, vh1, vc1);
        vgemm<128, 1><<<dim3(16, 8), 256, smem2>>>(vh1, vh2, Wih_v2, Whh_v2, part);
        vpw<<<128, 256>>>(part, nullptr, 0, b_v2, vh2, vc2);
    }

    // broadcast video-final states into text ping 0 (sorted rows)
    bc_init<<<640, 256>>>(vh1, vc1, vh2, vc2, h1, c1, h2, c2, perm);

    // ---- text recurrence (sorted rows, ragged early-exit) ----
    int p = 0;
    for (int t = 0; t < 20; t++) {
        int q = p ^ 1;
        cell_k3<16, 16, 4, 2, 0, 1, 0, 0><<<dim3(16, 5), 256>>>(
            h1 + p * SS, nullptr, Whh_t1, nullptr, nullptr,
            Xt1 + (long)t * 320 * 2048, 2048,
            c1 + p * SS, nh1, nc1,
            nullptr, nullptr, nullptr, nullptr, nullptr, qs, t);
        cell_k3<16, 16, 4, 2, 1, 0, 1, 1><<<dim3(16, 5), 256>>>(
            nh1, h2 + p * SS, Wih_t2, Whh_t2, b_t2,
            nullptr, 0,
            c2 + p * SS, h2 + q * SS, c2 + q * SS,
            nc1, h1 + p * SS, c1 + p * SS, h1 + q * SS, c1 + q * SS,
            qs, t);
        p = q;
    }

    // ---- decoder (scatter to original rows) ----
    dec1_k<<<dim3(8, 3), 256>>>(h1 + p * SS, h2 + p * SS, dec1_w, dec1_b, fe, perm);
    dec2_k<<<10, 1024>>>(fe, dec2_w, dec2_b, out);
    if (out_size >= 384)
        argmax_k<<<1, 64>>>(out, out + 320);
}

// round 11
// speedup vs baseline: 1.2430x; 1.2430x over previous
#include <cuda_runtime.h>

typedef unsigned long long ull;

#define SS   (320*512)      // text state buffer (rows*H)

// -------- device scratch (no allocation allowed) --------
__device__ float g_Xv1[1280L*2048];     // [B*F, 4H] rows (b*20+f): vf@Wih_v1^T + b_v1
__device__ float g_Xt1[6400L*2048];     // [L*BN, 4H] rows (l*320+sortedRow)
__device__ float g_part[8L*64*2048];    // split-K partials (video cells)
__device__ float g_vh1[64*512];         // video states (in-place)
__device__ float g_vc1[64*512];
__device__ float g_vh2[64*512];
__device__ float g_vc2[64*512];
__device__ float g_h1[2*SS];            // text ping-pong (sorted rows)
__device__ float g_c1[2*SS];
__device__ float g_h2[2*SS];
__device__ float g_c2[2*SS];
__device__ float g_nh1[SS];
__device__ float g_nc1[SS];
__device__ float g_fe[320*1024];
__device__ int   g_perm[320];           // sorted row -> original row
__device__ int   g_qs[320];             // qlen per sorted row (desc)

// ---- packed f32x2 helpers (lowered to 2xFFMA on sm_100a) ----
__device__ __forceinline__ ull pk2(float lo, float hi) {
    ull r;
    asm("mov.b64 %0, {%1, %2};" : "=l"(r) : "f"(lo), "f"(hi));
    return r;
}
__device__ __forceinline__ void upk2(ull v, float& lo, float& hi) {
    asm("mov.b64 {%0, %1}, %2;" : "=f"(lo), "=f"(hi) : "l"(v));
}
#define FMA2(acc, a, b) asm("fma.rn.f32x2 %0, %1, %2, %3;" : "=l"(acc) : "l"(a), "l"(b), "l"(acc))

__device__ __forceinline__ float sigf(float x) { return 1.f / (1.f + expf(-x)); }

// =====================================================================
// sortq: sort 64 batches by qlen descending; build row perm + qs.
// =====================================================================
__global__ void sortq(const int* __restrict__ qlen,
                      int* __restrict__ perm, int* __restrict__ qs)
{
    if (threadIdx.x == 0) {
        int idx[64];
        for (int i = 0; i < 64; i++) idx[i] = i;
        for (int i = 1; i < 64; i++) {
            int v = idx[i], qv = qlen[v], j = i - 1;
            while (j >= 0 && qlen[idx[j]] < qv) { idx[j + 1] = idx[j]; j--; }
            idx[j + 1] = v;
        }
        for (int s = 0; s < 320; s++) {
            int b = idx[s / 5];
            perm[s] = b * 5 + (s % 5);
            qs[s] = qlen[b];
        }
    }
}

// =====================================================================
// vgemm: split-K video cell GEMM (unchanged from R6, proven)
// =====================================================================
template<int KS, int CC>
__global__ __launch_bounds__(256)
void vgemm(const float* __restrict__ A, const float* __restrict__ A2,
           const float* __restrict__ W, const float* __restrict__ W2,
           float* __restrict__ part)
{
    extern __shared__ float sm[];
    float* As = sm;
    float* Bs = sm + 64 * KS;

    const int tid = threadIdx.x;
    const int n0 = blockIdx.x * 128;
    const int kbase = blockIdx.y * KS;

#pragma unroll
    for (int z = 0; z < KS / 16; z++) {
        int c = tid + z * 256;
        int m = c / (KS / 4), k4 = c % (KS / 4);
        int gk = kbase + k4 * 4;
        float4 v;
        if (!CC || gk < 512) v = *(const float4*)&A[m * 512 + gk];
        else                 v = *(const float4*)&A2[m * 512 + gk - 512];
        *(float4*)&As[m * KS + k4 * 4] = v;
    }
#pragma unroll
    for (int z = 0; z < KS / 8; z++) {
        int c = tid + z * 256;
        int n = c / (KS / 4), k4 = c % (KS / 4);
        int gk = kbase + k4 * 4;
        float4 v;
        if (!CC || gk < 512) v = *(const float4*)&W[(long)(n0 + n) * 512 + gk];
        else                 v = *(const float4*)&W2[(long)(n0 + n) * 512 + gk - 512];
        int nsw = n ^ ((k4 & 15) * 2);
        Bs[(k4 * 4 + 0) * 128 + nsw] = v.x;
        Bs[(k4 * 4 + 1) * 128 + nsw] = v.y;
        Bs[(k4 * 4 + 2) * 128 + nsw] = v.z;
        Bs[(k4 * 4 + 3) * 128 + nsw] = v.w;
    }
    __syncthreads();

    const int tx = tid & 15, ty = tid >> 4;
    ull acc[4][4];
#pragma unroll
    for (int rm = 0; rm < 4; rm++)
#pragma unroll
        for (int s = 0; s < 4; s++) acc[rm][s] = 0ull;

#pragma unroll 4
    for (int kk = 0; kk < KS; kk++) {
        const int swr = ((kk >> 2) & 15) * 2;
        ull b[4];
#pragma unroll
        for (int s = 0; s < 4; s++)
            b[s] = *(const ull*)&Bs[kk * 128 + ((tx * 2 + s * 32) ^ swr)];
#pragma unroll
        for (int rm = 0; rm < 4; rm++) {
            float a = As[(ty * 4 + rm) * KS + kk];
            ull ad = pk2(a, a);
            FMA2(acc[rm][0], ad, b[0]);
            FMA2(acc[rm][1], ad, b[1]);
            FMA2(acc[rm][2], ad, b[2]);
            FMA2(acc[rm][3], ad, b[3]);
        }
    }

    float* op = part + (long)blockIdx.y * (64 * 2048) + n0;
#pragma unroll
    for (int rm = 0; rm < 4; rm++) {
        int m = ty * 4 + rm;
#pragma unroll
        for (int s = 0; s < 4; s++) {
            float lo, hi;
            upk2(acc[rm][s], lo, hi);
            *(float2*)&op[(long)m * 2048 + tx * 2 + s * 32] = make_float2(lo, hi);
        }
    }
}

// video pointwise: sum 8 partials (+xpre or +bias), LSTM update in-place.
__global__ void vpw(const float* __restrict__ part,
                    const float* __restrict__ xpre, long xstride,
                    const float* __restrict__ bias,
                    float* __restrict__ h, float* __restrict__ c)
{
    int idx = blockIdx.x * 256 + threadIdx.x;
    int m = idx >> 9, j = idx & 511;
    float g[4];
#pragma unroll
    for (int gi = 0; gi < 4; gi++) {
        int col = gi * 512 + j;
        float s = bias ? bias[col] : xpre[(long)m * xstride + col];
#pragma unroll
        for (int z = 0; z < 8; z++)
            s += part[(long)z * 64 * 2048 + (long)m * 2048 + col];
        g[gi] = s;
    }
    float cc = sigf(g[1]) * c[idx] + sigf(g[0]) * tanhf(g[2]);
    c[idx] = cc;
    h[idx] = sigf(g[3]) * tanhf(cc);
}

// =====================================================================
// cell_k3: fused text LSTM cell + qlen-sorted early exit.
// Retiled for full-chip balance: TM=32, TJ=16 -> grid (32,10)=320 blocks
// with multi-block-per-SM residency (smem 13.3KB). Early exit pays:
// blocks queue across waves, so skipped blocks free SMs.
// =====================================================================
template<int TY, int TX, int RM, int RJ, int CC, int HX, int HB, int MK>
__global__ __launch_bounds__(256)
void cell_k3(const float* __restrict__ A, const float* __restrict__ A2,
             const float* __restrict__ W, const float* __restrict__ W2,
             const float* __restrict__ bias,
             const float* __restrict__ xpre, int xstride,
             const float* __restrict__ c_in,
             float* __restrict__ h_out, float* __restrict__ c_out,
             const float* __restrict__ nc1p,
             const float* __restrict__ h1_in, const float* __restrict__ c1_in,
             float* __restrict__ h1_o, float* __restrict__ c1_o,
             const int* __restrict__ qlen, int t)
{
    constexpr int TM = TY * RM;
    constexpr int TJ = TX * RJ;
    constexpr int GC = 4 * TJ;
    constexpr int K  = CC ? 1024 : 512;
    constexpr int BK = 16;
    constexpr int ASTR = TM + 4;
    constexpr int BSTR = GC + 4;
    constexpr int NCA = (TM * 4 + 255) / 256;    // guarded chunks
    constexpr int NCB = (GC * 4 + 255) / 256;

    // ragged early exit (rows sorted desc -> row m0 holds the block max;
    // at t == qlen the freeze-commit ran, so both pings hold frozen state)
    if (t > __ldg(&qlen[blockIdx.y * TM])) return;

    __shared__ float As[2][BK * ASTR];
    __shared__ float Bs[2][BK * BSTR];

    const int tid = threadIdx.x;
    const int tx  = tid % TX;
    const int ty  = tid / TX;
    const int m0  = blockIdx.y * TM;
    const int j0  = blockIdx.x * TJ;

    float4 pa[NCA], pb[NCB];

    auto ldg = [&](int kb) {
#pragma unroll
        for (int z = 0; z < NCA; z++) {
            int i = tid + z * 256;
            if (i < TM * 4) {
                int row = i >> 2, kq = (i & 3) * 4;
                int m = m0 + row, k = kb + kq;
                pa[z] = CC ? ((k < 512) ? *(const float4*)&A[(long)m * 512 + k]
                                        : *(const float4*)&A2[(long)m * 512 + (k - 512)])
                           : *(const float4*)&A[(long)m * 512 + k];
            }
        }
#pragma unroll
        for (int z = 0; z < NCB; z++) {
            int i = tid + z * 256;
            if (i < GC * 4) {
                int r = i >> 2, kq = (i & 3) * 4;
                int jl = r >> 2, g = r & 3;
                int wr = g * 512 + j0 + jl, k = kb + kq;
                pb[z] = CC ? ((k < 512) ? *(const float4*)&W[(long)wr * 512 + k]
                                        : *(const float4*)&W2[(long)wr * 512 + (k - 512)])
                           : *(const float4*)&W[(long)wr * 512 + k];
            }
        }
    };
    auto sts = [&](int s) {
#pragma unroll
        for (int z = 0; z < NCA; z++) {
            int i = tid + z * 256;
            if (i < TM * 4) {
                int row = i >> 2, kq = (i & 3) * 4;
                As[s][(kq + 0) * ASTR + row] = pa[z].x;
                As[s][(kq + 1) * ASTR + row] = pa[z].y;
                As[s][(kq + 2) * ASTR + row] = pa[z].z;
                As[s][(kq + 3) * ASTR + row] = pa[z].w;
            }
        }
#pragma unroll
        for (int z = 0; z < NCB; z++) {
            int i = tid + z * 256;
            if (i < GC * 4) {
                int r = i >> 2, kq = (i & 3) * 4;
                Bs[s][(kq + 0) * BSTR + r] = pb[z].x;
                Bs[s][(kq + 1) * BSTR + r] = pb[z].y;
                Bs[s][(kq + 2) * BSTR + r] = pb[z].z;
                Bs[s][(kq + 3) * BSTR + r] = pb[z].w;
            }
        }
    };

    ull acc[RM][RJ][2];
#pragma unroll
    for (int im = 0; im < RM; im++)
#pragma unroll
        for (int ij = 0; ij < RJ; ij++) { acc[im][ij][0] = 0ull; acc[im][ij][1] = 0ull; }

    ldg(0); sts(0); __syncthreads();
    constexpr int NKT = K / BK;
    for (int kt = 0; kt < NKT; kt++) {
        const int s = kt & 1;
        if (kt + 1 < NKT) ldg((kt + 1) * BK);
#pragma unroll
        for (int kk = 0; kk < BK; kk++) {
            ull ad[RM];
            if (RM == 4) {
                const float4 av = *(const float4*)&As[s][kk * ASTR + ty * RM];
                ad[0] = pk2(av.x, av.x); ad[1] = pk2(av.y, av.y);
                ad[2] = pk2(av.z, av.z); ad[3] = pk2(av.w, av.w);
            } else {
                const float2 av = *(const float2*)&As[s][kk * ASTR + ty * RM];
                ad[0] = pk2(av.x, av.x); ad[1] = pk2(av.y, av.y);
            }
#pragma unroll
            for (int ij = 0; ij < RJ; ij++) {
                const ulonglong2 bv =
                    *(const ulonglong2*)&Bs[s][kk * BSTR + (tx * RJ + ij) * 4];
#pragma unroll
                for (int im = 0; im < RM; im++) {
                    FMA2(acc[im][ij][0], ad[im], bv.x);
                    FMA2(acc[im][ij][1], ad[im], bv.y);
                }
            }
        }
        if (kt + 1 < NKT) sts(s ^ 1);
        __syncthreads();
    }

#pragma unroll
    for (int im = 0; im < RM; im++) {
#pragma unroll
        for (int ij = 0; ij < RJ; ij++) {
            int m = m0 + ty * RM + im;
            int j = j0 + tx * RJ + ij;
            int idx = m * 512 + j;
            float vi, vf, vg, vo;
            upk2(acc[im][ij][0], vi, vf);
            upk2(acc[im][ij][1], vg, vo);
            if (HX) {
                const float* xr = xpre + (long)m * xstride;
                vi += xr[j]; vf += xr[512 + j]; vg += xr[1024 + j]; vo += xr[1536 + j];
            }
            if (HB) {
                vi += bias[j]; vf += bias[512 + j]; vg += bias[1024 + j]; vo += bias[1536 + j];
            }
            float c = sigf(vf) * c_in[idx] + sigf(vi) * tanhf(vg);
            float h = sigf(vo) * tanhf(c);
            if (!MK) {
                c_out[idx] = c;
                h_out[idx] = h;
            } else {
                bool upd = t < qlen[m];               // per-sorted-row qlen
                h_out[idx] = upd ? h : A2[idx];       // A2 = old h2
                c_out[idx] = upd ? c : c_in[idx];     // c_in = old c2
                h1_o[idx]  = upd ? A[idx] : h1_in[idx];
                c1_o[idx]  = upd ? nc1p[idx] : c1_in[idx];
            }
        }
    }
}

// =====================================================================
// sgemm3 (R6, proven): 128x64xK GEMM, BK=16 double-buffered, f32x2.
// AM: 0 = direct, 2 = embedding gather (SORTED row space via perm).
// =====================================================================
template<int AM>
__global__ __launch_bounds__(256)
void sgemm3(const float* __restrict__ A, const float* __restrict__ W,
            const float* __restrict__ bias, float* __restrict__ out,
            int Kfull, int lda,
            const int* __restrict__ ques, const float* __restrict__ emb,
            const int* __restrict__ perm)
{
    constexpr int BK = 16, ASTR = 132, BSTR = 68;
    __shared__ float As[2][BK * ASTR];
    __shared__ float Bs[2][BK * BSTR];

    const int tid = threadIdx.x;
    const int tx  = tid & 15;
    const int ty  = tid >> 4;
    const int m0  = blockIdx.y * 128;
    const int n0  = blockIdx.x * 64;

    float4 pa[2], pb;

    auto ldg = [&](int kb) {
#pragma unroll
        for (int z = 0; z < 2; z++) {
            int c = tid + z * 256, row = c >> 2, kq = (c & 3) * 4;
            int m = m0 + row, k = kb + kq;
            if (AM == 0) {
                pa[z] = *(const float4*)&A[(long)m * lda + k];
            } else {
                int qq = m % 320, l = m / 320;
                long tb = (long)ques[perm[qq] * 20 + l] * 300;
                float v[4];
#pragma unroll
                for (int i = 0; i < 4; i++) {
                    int kk = k + i;
                    v[i] = (kk < Kfull) ? emb[tb + kk] : 0.f;
                }
                pa[z] = make_float4(v[0], v[1], v[2], v[3]);
            }
        }
        {
            int c = tid, r = c >> 2, kq = (c & 3) * 4;
            int n = n0 + r, k = kb + kq;
            if (AM == 0) {
                pb = *(const float4*)&W[(long)n * lda + k];
            } else {
                float v[4];
#pragma unroll
                for (int i = 0; i < 4; i++)
                    v[i] = (k + i < Kfull) ? W[(long)n * Kfull + k + i] : 0.f;
                pb = make_float4(v[0], v[1], v[2], v[3]);
            }
        }
    };
    auto sts = [&](int s) {
#pragma unroll
        for (int z = 0; z < 2; z++) {
            int c = tid + z * 256, row = c >> 2, kq = (c & 3) * 4;
            As[s][(kq + 0) * ASTR + row] = pa[z].x;
            As[s][(kq + 1) * ASTR + row] = pa[z].y;
            As[s][(kq + 2) * ASTR + row] = pa[z].z;
            As[s][(kq + 3) * ASTR + row] = pa[z].w;
        }
        {
            int c = tid, r = c >> 2, kq = (c & 3) * 4;
            Bs[s][(kq + 0) * BSTR + r] = pb.x;
            Bs[s][(kq + 1) * BSTR + r] = pb.y;
            Bs[s][(kq + 2) * BSTR + r] = pb.z;
            Bs[s][(kq + 3) * BSTR + r] = pb.w;
        }
    };

    ull acc[8][2];
#pragma unroll
    for (int i = 0; i < 8; i++) { acc[i][0] = 0ull; acc[i][1] = 0ull; }

    ldg(0); sts(0); __syncthreads();
    const int nkt = (Kfull + BK - 1) / BK;
    for (int kt = 0; kt < nkt; kt++) {
        const int s = kt & 1;
        if (kt + 1 < nkt) ldg((kt + 1) * BK);
#pragma unroll
        for (int kk = 0; kk < BK; kk++) {
            const float4 a0 = *(const float4*)&As[s][kk * ASTR + ty * 8];
            const float4 a1 = *(const float4*)&As[s][kk * ASTR + ty * 8 + 4];
            const ulonglong2 bv = *(const ulonglong2*)&Bs[s][kk * BSTR + tx * 4];
            float av[8] = { a0.x, a0.y, a0.z, a0.w, a1.x, a1.y, a1.z, a1.w };
#pragma unroll
            for (int im = 0; im < 8; im++) {
                ull ad = pk2(av[im], av[im]);
                FMA2(acc[im][0], ad, bv.x);
                FMA2(acc[im][1], ad, bv.y);
            }
        }
        if (kt + 1 < nkt) sts(s ^ 1);
        __syncthreads();
    }

#pragma unroll
    for (int im = 0; im < 8; im++) {
        int m = m0 + ty * 8 + im;
        long ro = (long)m * 2048 + n0 + tx * 4;
        float v0, v1, v2, v3;
        upk2(acc[im][0], v0, v1);
        upk2(acc[im][1], v2, v3);
        if (bias) {
            v0 += bias[n0 + tx * 4 + 0]; v1 += bias[n0 + tx * 4 + 1];
            v2 += bias[n0 + tx * 4 + 2]; v3 += bias[n0 + tx * 4 + 3];
        }
        out[ro + 0] = v0; out[ro + 1] = v1; out[ro + 2] = v2; out[ro + 3] = v3;
    }
}

// broadcast video-final states [64,512] -> text-init [320,512] (sorted rows)
__global__ void bc_init(const float* __restrict__ sh1, const float* __restrict__ sc1,
                        const float* __restrict__ sh2, const float* __restrict__ sc2,
                        float* __restrict__ dh1, float* __restrict__ dc1,
                        float* __restrict__ dh2, float* __restrict__ dc2,
                        const int* __restrict__ perm)
{
    int idx = blockIdx.x * blockDim.x + threadIdx.x;
    if (idx >= 320 * 512) return;
    int q = idx >> 9, j = idx & 511;
    int s = (perm[q] / 5) * 512 + j;
    dh1[idx] = sh1[s]; dc1[idx] = sc1[s];
    dh2[idx] = sh2[s]; dc2[idx] = sc2[s];
}

// ---- decoder (sorted-space input, scatter to original rows) ----
__global__ __launch_bounds__(256)
void dec1_k(const float* __restrict__ A, const float* __restrict__ A2,
            const float* __restrict__ W, const float* __restrict__ bias,
            float* __restrict__ out, const int* __restrict__ perm)
{
    __shared__ float As[8][128];
    __shared__ float Bs[8][128];
    const int tid = threadIdx.x;
    const int r   = tid >> 1;
    const int kq  = (tid & 1) * 4;
    const int m0  = blockIdx.y * 128;
    const int n0  = blockIdx.x * 128;
    const int tx  = tid & 15;
    const int ty  = tid >> 4;
    const int m   = m0 + r;
    const int n   = n0 + r;

    float acc[8][8];
#pragma unroll
    for (int i = 0; i < 8; i++)
#pragma unroll
        for (int jj = 0; jj < 8; jj++) acc[i][jj] = 0.f;

    for (int kt = 0; kt < 128; kt++) {
        const int kb = kt * 8;
#pragma unroll
        for (int i = 0; i < 4; i++) {
            int k = kb + kq + i;
            As[kq + i][r] = (m < 320) ? ((k < 512) ? A[(long)m * 512 + k]
                                                   : A2[(long)m * 512 + (k - 512)]) : 0.f;
            Bs[kq + i][r] = W[(long)n * 1024 + k];
        }
        __syncthreads();
#pragma unroll
        for (int kk = 0; kk < 8; kk++) {
            float a[8], b[8];
#pragma unroll
            for (int i = 0; i < 8; i++) a[i] = As[kk][ty * 8 + i];
#pragma unroll
            for (int jj = 0; jj < 8; jj++) b[jj] = Bs[kk][tx * 8 + jj];
#pragma unroll
            for (int i = 0; i < 8; i++)
#pragma unroll
                for (int jj = 0; jj < 8; jj++) acc[i][jj] += a[i] * b[jj];
        }
        __syncthreads();
    }
#pragma unroll
    for (int i = 0; i < 8; i++) {
        int mm = m0 + ty * 8 + i;
        if (mm < 320) {
            long ro = (long)perm[mm] * 1024 + n0 + tx * 8;
#pragma unroll
            for (int jj = 0; jj < 8; jj++)
                out[ro + jj] = acc[i][jj] + bias[n0 + tx * 8 + jj];
        }
    }
}

__global__ void dec2_k(const float* __restrict__ fe, const float* __restrict__ w,
                       const float* __restrict__ b, float* __restrict__ out)
{
    int warp = (blockIdx.x * blockDim.x + threadIdx.x) >> 5;
    int lane = threadIdx.x & 31;
    if (warp >= 320) return;
    float s = 0.f;
    for (int k = lane; k < 1024; k += 32) s += fe[(long)warp * 1024 + k] * w[k];
#pragma unroll
    for (int o = 16; o; o >>= 1) s += __shfl_xor_sync(0xFFFFFFFFu, s, o);
    if (lane == 0) out[warp] = s + b[0];
}

__global__ void argmax_k(const float* __restrict__ outv, float* __restrict__ pred)
{
    int b = threadIdx.x;
    if (b < 64) {
        float best = outv[b * 5]; int bi = 0;
#pragma unroll
        for (int n = 1; n < 5; n++) {
            float v = outv[b * 5 + n];
            if (v > best) { best = v; bi = n; }
        }
        pred[b] = (float)bi;
    }
}

// ---------------- host orchestration ----------------
extern "C" void kernel_launch(void* const* d_in, const int* in_sizes, int n_in,
                              void* d_out, int out_size)
{
    const float* vf      = (const float*)d_in[0];
    const int*   ques    = (const int*)  d_in[1];
    const int*   qlen    = (const int*)  d_in[2];
    const float* embed   = (const float*)d_in[3];
    const float* Wih_t1  = (const float*)d_in[4];
    const float* Whh_t1  = (const float*)d_in[5];
    const float* b_t1    = (const float*)d_in[6];
    const float* Wih_t2  = (const float*)d_in[7];
    const float* Whh_t2  = (const float*)d_in[8];
    const float* b_t2    = (const float*)d_in[9];
    const float* Wih_v1  = (const float*)d_in[10];
    const float* Whh_v1  = (const float*)d_in[11];
    const float* b_v1    = (const float*)d_in[12];
    const float* Wih_v2  = (const float*)d_in[13];
    const float* Whh_v2  = (const float*)d_in[14];
    const float* b_v2    = (const float*)d_in[15];
    const float* dec1_w  = (const float*)d_in[16];
    const float* dec1_b  = (const float*)d_in[17];
    const float* dec2_w  = (const float*)d_in[18];
    const float* dec2_b  = (const float*)d_in[19];
    float* out = (float*)d_out;

    float *Xv1, *Xt1, *part, *vh1, *vc1, *vh2, *vc2;
    float *h1, *c1, *h2, *c2, *nh1, *nc1, *fe;
    int *perm, *qs;
    cudaGetSymbolAddress((void**)&Xv1, g_Xv1);
    cudaGetSymbolAddress((void**)&Xt1, g_Xt1);
    cudaGetSymbolAddress((void**)&part, g_part);
    cudaGetSymbolAddress((void**)&vh1, g_vh1);
    cudaGetSymbolAddress((void**)&vc1, g_vc1);
    cudaGetSymbolAddress((void**)&vh2, g_vh2);
    cudaGetSymbolAddress((void**)&vc2, g_vc2);
    cudaGetSymbolAddress((void**)&h1,  g_h1);
    cudaGetSymbolAddress((void**)&c1,  g_c1);
    cudaGetSymbolAddress((void**)&h2,  g_h2);
    cudaGetSymbolAddress((void**)&c2,  g_c2);
    cudaGetSymbolAddress((void**)&nh1, g_nh1);
    cudaGetSymbolAddress((void**)&nc1, g_nc1);
    cudaGetSymbolAddress((void**)&fe,  g_fe);
    cudaGetSymbolAddress((void**)&perm, g_perm);
    cudaGetSymbolAddress((void**)&qs,   g_qs);

    // zero video initial states
    cudaMemsetAsync(vh1, 0, 64 * 512 * sizeof(float));
    cudaMemsetAsync(vc1, 0, 64 * 512 * sizeof(float));
    cudaMemsetAsync(vh2, 0, 64 * 512 * sizeof(float));
    cudaMemsetAsync(vc2, 0, 64 * 512 * sizeof(float));

    // sort batches by qlen (desc) -> row perm + per-row qlen
    sortq<<<1, 32>>>(qlen, perm, qs);

    // Xv1 = vf @ Wih_v1^T + b_v1 : [1280, 2048], K=8192
    sgemm3<0><<<dim3(32, 10), 256>>>(vf, Wih_v1, b_v1, Xv1, 8192, 8192,
                                     nullptr, nullptr, nullptr);
    // Xt1 = emb @ Wih_t1^T + b_t1 in SORTED row space
    sgemm3<2><<<dim3(32, 50), 256>>>(nullptr, Wih_t1, b_t1, Xt1, 300, 300,
                                     ques, embed, perm);

    // smem attrs for video split-K cells
    const int smem1 = (64 * 64 + 64 * 128) * 4;
    const int smem2 = (64 * 128 + 128 * 128) * 4;
    cudaFuncSetAttribute(vgemm<64, 0>, cudaFuncAttributeMaxDynamicSharedMemorySize, smem1);
    cudaFuncSetAttribute(vgemm<128, 1>, cudaFuncAttributeMaxDynamicSharedMemorySize, smem2);

    // ---- video recurrence: split-K GEMM + pointwise, in-place states ----
    for (int t = 0; t < 20; t++) {
        vgemm<64, 0><<<dim3(16, 8), 256, smem1>>>(vh1, nullptr, Whh_v1, nullptr, part);
        vpw<<<128, 256>>>(part, Xv1 + (long)t * 2048, 20 * 2048, nullptr, vh1, vc1);
        vgemm<128, 1><<<dim3(16, 8), 256, smem2>>>(vh1, vh2, Wih_v2, Whh_v2, part);
        vpw<<<128, 256>>>(part, nullptr, 0, b_v2, vh2, vc2);
    }

    // broadcast video-final states into text ping 0 (sorted rows)
    bc_init<<<640, 256>>>(vh1, vc1, vh2, vc2, h1, c1, h2, c2, perm);

    // ---- text recurrence (sorted rows, retiled 320 blocks, early-exit) ----
    int p = 0;
    for (int t = 0; t < 20; t++) {
        int q = p ^ 1;
        cell_k3<16, 16, 2, 1, 0, 1, 0, 0><<<dim3(32, 10), 256>>>(
            h1 + p * SS, nullptr, Whh_t1, nullptr, nullptr,
            Xt1 + (long)t * 320 * 2048, 2048,
            c1 + p * SS, nh1, nc1,
            nullptr, nullptr, nullptr, nullptr, nullptr, qs, t);
        cell_k3<16, 16, 2, 1, 1, 0, 1, 1><<<dim3(32, 10), 256>>>(
            nh1, h2 + p * SS, Wih_t2, Whh_t2, b_t2,
            nullptr, 0,
            c2 + p * SS, h2 + q * SS, c2 + q * SS,
            nc1, h1 + p * SS, c1 + p * SS, h1 + q * SS, c1 + q * SS,
            qs, t);
        p = q;
    }

    // ---- decoder (scatter to original rows) ----
    dec1_k<<<dim3(8, 3), 256>>>(h1 + p * SS, h2 + p * SS, dec1_w, dec1_b, fe, perm);
    dec2_k<<<10, 1024>>>(fe, dec2_w, dec2_b, out);
    if (out_size >= 384)
        argmax_k<<<1, 64>>>(out, out + 320);
}